// round 2
// baseline (speedup 1.0000x reference)
#include <cuda_runtime.h>
#include <cuda_bf16.h>
#include <cstdint>

// Problem-fixed shapes: E=4096, IN=OUT=256, N_NODES=1024
#define MAX_E 4096
#define NN    1024
#define OUTC  256

// ---------------- device scratch ----------------
__device__ float g_s[MAX_E];          // sign per edge: -1 if directed else +1
__device__ float g_w[MAX_E];          // s_e * dinv_e
__device__ int   g_off_src[NN + 1], g_off_dst[NN + 1];
__device__ int   g_lst_src[MAX_E], g_lst_dst[MAX_E];
__device__ float g_h[MAX_E * OUTC];   // h = x @ W^T

// ================= K1: fused build (signs + CSR for src and dst) ==========
// Single block, 1024 threads. Counts and scans live entirely in smem.
__global__ __launch_bounds__(1024)
void k_build(const void* __restrict__ isdir, const int* __restrict__ ei, int E) {
    __shared__ int cs[NN];
    __shared__ int cd[NN];
    __shared__ int s_any;
    int t = threadIdx.x;

    if (t == 0) s_any = 0;
    cs[t] = 0; cd[t] = 0;
    __syncthreads();

    // detect is_directed storage: byte bools have nonzero bytes at i%4!=0
    const unsigned char* b = (const unsigned char*)isdir;
    int local = 0;
    for (int i = t; i < E; i += 1024)
        if ((i & 3) != 0) local |= b[i];
    if (local) atomicOr(&s_any, 1);
    __syncthreads();
    bool byte_layout = (s_any != 0);
    const int* bi = (const int*)isdir;

    // signs + counts
    for (int e = t; e < E; e += 1024) {
        int d = byte_layout ? (b[e] != 0) : (bi[e] != 0);
        g_s[e] = d ? -1.0f : 1.0f;
        atomicAdd(&cs[ei[e]], 1);
        atomicAdd(&cd[ei[E + e]], 1);
    }
    __syncthreads();

    // inclusive Hillis-Steele scan on both arrays (NN==1024 threads)
    for (int off = 1; off < NN; off <<= 1) {
        int vs = (t >= off) ? cs[t - off] : 0;
        int vd = (t >= off) ? cd[t - off] : 0;
        __syncthreads();
        cs[t] += vs; cd[t] += vd;
        __syncthreads();
    }
    g_off_src[t + 1] = cs[t];
    g_off_dst[t + 1] = cd[t];
    if (t == 0) { g_off_src[0] = 0; g_off_dst[0] = 0; }
    __syncthreads();

    // reuse count arrays as running cursors
    cs[t] = 0; cd[t] = 0;
    __syncthreads();

    // fill lists
    for (int e = t; e < E; e += 1024) {
        int s = ei[e], d = ei[E + e];
        int p = g_off_src[s] + atomicAdd(&cs[s], 1);
        g_lst_src[p] = e;
        int q = g_off_dst[d] + atomicAdd(&cd[d], 1);
        g_lst_dst[q] = e;
    }
}

// ================= K2: fused GEMM + degree =================================
#define BM 128
#define BN 64
#define BK 16
#define TM 8
#define TN 4

__global__ __launch_bounds__(256, 2)
void k_mid(const float* __restrict__ A,   // x  [E, K]
           const float* __restrict__ B,   // W  [N, K]
           float* __restrict__ C,         // h  [E, N]
           const int* __restrict__ ei,
           int E, int N, int K,
           int gemmGridX, int gemmBlocks) {
    if ((int)blockIdx.x < gemmBlocks) {
        // ---------------- GEMM part: h = x @ W^T ----------------
        __shared__ float As[BK][BM + 1];
        __shared__ float Bs[BK][BN + 1];
        int gx = blockIdx.x % gemmGridX;
        int gy = blockIdx.x / gemmGridX;
        int m0 = gy * BM;
        int n0 = gx * BN;
        int tid = threadIdx.x;
        int tx = tid % 16;
        int ty = tid / 16;

        float acc[TM][TN];
        #pragma unroll
        for (int i = 0; i < TM; i++)
            #pragma unroll
            for (int j = 0; j < TN; j++) acc[i][j] = 0.0f;

        for (int k0 = 0; k0 < K; k0 += BK) {
            #pragma unroll
            for (int r = 0; r < 2; r++) {
                int idx = tid + 256 * r;
                int row = idx >> 2;
                int kq  = (idx & 3) << 2;
                float4 v = *(const float4*)&A[(size_t)(m0 + row) * K + k0 + kq];
                As[kq + 0][row] = v.x; As[kq + 1][row] = v.y;
                As[kq + 2][row] = v.z; As[kq + 3][row] = v.w;
            }
            {
                int n  = tid >> 2;
                int kq = (tid & 3) << 2;
                float4 v = *(const float4*)&B[(size_t)(n0 + n) * K + k0 + kq];
                Bs[kq + 0][n] = v.x; Bs[kq + 1][n] = v.y;
                Bs[kq + 2][n] = v.z; Bs[kq + 3][n] = v.w;
            }
            __syncthreads();

            #pragma unroll
            for (int k = 0; k < BK; k++) {
                float a[TM], bb[TN];
                #pragma unroll
                for (int i = 0; i < TM; i++) a[i] = As[k][ty * TM + i];
                #pragma unroll
                for (int j = 0; j < TN; j++) bb[j] = Bs[k][tx * TN + j];
                #pragma unroll
                for (int i = 0; i < TM; i++)
                    #pragma unroll
                    for (int j = 0; j < TN; j++)
                        acc[i][j] = fmaf(a[i], bb[j], acc[i][j]);
            }
            __syncthreads();
        }

        #pragma unroll
        for (int i = 0; i < TM; i++) {
            float4 v = make_float4(acc[i][0], acc[i][1], acc[i][2], acc[i][3]);
            *(float4*)&C[(size_t)(m0 + ty * TM + i) * N + n0 + tx * TN] = v;
        }
    } else {
        // ---------------- degree part: g_w[e] = s_e / sqrt(deg_e) ----------
        int db   = blockIdx.x - gemmBlocks;
        int warp = db * 8 + ((int)threadIdx.x >> 5);
        int lane = threadIdx.x & 31;
        if (warp >= E) return;
        int e = warp;
        int se = ei[e], de = ei[E + e];
        float acc = 0.0f;
        #pragma unroll
        for (int pass = 0; pass < 4; pass++) {
            int node = (pass < 2) ? se : de;
            const int* lst; int lo, hi;
            if (pass & 1) { lo = g_off_dst[node]; hi = g_off_dst[node + 1]; lst = g_lst_dst; }
            else          { lo = g_off_src[node]; hi = g_off_src[node + 1]; lst = g_lst_src; }
            for (int j = lo + lane; j < hi; j += 32) {
                int f = lst[j];
                int sf = ei[f], df = ei[E + f];
                int ss = (sf == se), sd = (df == se), ds = (sf == de), dd = (df == de);
                int c = ss + dd - sd - ds;
                int k = ss + sd + ds + dd;      // multiplicity across the 4 lists
                acc += fabsf((float)c) / (float)k;
            }
        }
        #pragma unroll
        for (int o = 16; o; o >>= 1) acc += __shfl_down_sync(0xffffffffu, acc, o);
        if (lane == 0)
            g_w[e] = (acc > 0.0f) ? (g_s[e] * rsqrtf(acc)) : 0.0f;
    }
}

// ================= K3: y = D^-1/2 L D^-1/2 h (warp per edge) ==============
__global__ __launch_bounds__(256)
void k_y(const int* __restrict__ ei, float* __restrict__ y, int E) {
    int warp = (blockIdx.x * blockDim.x + threadIdx.x) >> 5;
    int lane = threadIdx.x & 31;
    if (warp >= E) return;
    int e = warp;
    int se = ei[e], de = ei[E + e];

    float acc[8];
    #pragma unroll
    for (int i = 0; i < 8; i++) acc[i] = 0.0f;

    #pragma unroll
    for (int pass = 0; pass < 4; pass++) {
        int node = (pass < 2) ? se : de;
        const int* lst; int lo, hi;
        if (pass & 1) { lo = g_off_dst[node]; hi = g_off_dst[node + 1]; lst = g_lst_dst; }
        else          { lo = g_off_src[node]; hi = g_off_src[node + 1]; lst = g_lst_src; }
        for (int j = lo; j < hi; j++) {          // uniform across warp
            int f = lst[j];
            int sf = ei[f], df = ei[E + f];
            int ss = (sf == se), sd = (df == se), ds = (sf == de), dd = (df == de);
            int c = ss + dd - sd - ds;
            int k = ss + sd + ds + dd;
            float w = ((float)c / (float)k) * g_w[f];
            if (w != 0.0f) {
                const float4* hp = (const float4*)&g_h[(size_t)f * OUTC + lane * 8];
                float4 v0 = hp[0], v1 = hp[1];
                acc[0] = fmaf(w, v0.x, acc[0]); acc[1] = fmaf(w, v0.y, acc[1]);
                acc[2] = fmaf(w, v0.z, acc[2]); acc[3] = fmaf(w, v0.w, acc[3]);
                acc[4] = fmaf(w, v1.x, acc[4]); acc[5] = fmaf(w, v1.y, acc[5]);
                acc[6] = fmaf(w, v1.z, acc[6]); acc[7] = fmaf(w, v1.w, acc[7]);
            }
        }
    }
    float sc = g_w[e];
    float4 o0 = make_float4(acc[0] * sc, acc[1] * sc, acc[2] * sc, acc[3] * sc);
    float4 o1 = make_float4(acc[4] * sc, acc[5] * sc, acc[6] * sc, acc[7] * sc);
    float4* op = (float4*)&y[(size_t)e * OUTC + lane * 8];
    op[0] = o0; op[1] = o1;
}

// ---------------- launch ---------------------------------------------------
extern "C" void kernel_launch(void* const* d_in, const int* in_sizes, int n_in,
                              void* d_out, int out_size) {
    const float* x     = (const float*)d_in[0];   // [E, IN]
    const float* W     = (const float*)d_in[1];   // [OUT, IN]
    const int*   ei    = (const int*)d_in[2];     // [2, E]
    const void*  isdir = d_in[3];                 // [E] bool or int32

    int E   = in_sizes[2] / 2;
    int IN  = in_sizes[0] / E;
    int OUT = in_sizes[1] / IN;
    float* y = (float*)d_out;

    float* h = nullptr;
    cudaGetSymbolAddress((void**)&h, g_h);

    // 1) build signs + CSR in a single block
    k_build<<<1, 1024>>>(isdir, ei, E);

    // 2) fused GEMM + degree
    int gemmGridX  = OUT / BN;                 // 4
    int gemmBlocks = gemmGridX * (E / BM);     // 128
    int degBlocks  = (E + 7) / 8;              // 512
    k_mid<<<gemmBlocks + degBlocks, 256>>>(x, W, h, ei, E, OUT, IN,
                                           gemmGridX, gemmBlocks);

    // 3) sparse Laplacian apply
    k_y<<<(E + 7) / 8, 256>>>(ei, y, E);
}

// round 3
// speedup vs baseline: 2.1896x; 2.1896x over previous
#include <cuda_runtime.h>
#include <cstdint>

// Fixed problem shapes: E=4096, IN=OUT=256, N_NODES=1024
#define MAX_E 4096
#define NN    1024
#define FC    256          // feature channels (IN == OUT == 256)
#define FC4   64           // float4 chunks per row

// ---------------- device scratch ----------------
__device__ int   g_flagA;            // nonzero byte at misaligned index -> byte layout
__device__ int   g_flagNZ;           // any nonzero byte
__device__ int   g_hs[NN], g_hd[NN], g_sl[NN];
__device__ float g_w[MAX_E];         // s_e / sqrt(deg_e)  (0 for self-loops)
__device__ float g_t[NN * FC];       // t = B (w .* x)
__device__ float g_T[NN * FC];       // T = t @ W^T

// ============ K0: zero accumulators (graph-replay safe) ====================
__global__ void k_zero() {
    int i = blockIdx.x * blockDim.x + threadIdx.x;     // 65536 threads
    ((float4*)g_t)[i] = make_float4(0.f, 0.f, 0.f, 0.f);
    if (i < NN) { g_hs[i] = 0; g_hd[i] = 0; g_sl[i] = 0; }
    if (i == NN) { g_flagA = 0; g_flagNZ = 0; }
}

// ============ K1: per-edge histograms + bool-layout detection ==============
__global__ void k_hist(const int* __restrict__ ei,
                       const unsigned char* __restrict__ b, int E) {
    int e = blockIdx.x * blockDim.x + threadIdx.x;
    if (e >= E) return;
    unsigned char v = b[e];                            // safe: buffer >= E bytes
    if (v) {
        atomicOr(&g_flagNZ, 1);
        if (e & 3) atomicOr(&g_flagA, 1);
    }
    int s = ei[e], d = ei[E + e];
    atomicAdd(&g_hs[s], 1);
    atomicAdd(&g_hd[d], 1);
    if (s == d) atomicAdd(&g_sl[s], 1);
}

// ============ K2: per-edge weight w_e = s_e / sqrt(deg_e) ==================
__global__ void k_wgt(const int* __restrict__ ei, const void* __restrict__ isdir,
                      int E) {
    int e = blockIdx.x * blockDim.x + threadIdx.x;
    if (e >= E) return;
    int s = ei[e], d = ei[E + e];
    float w = 0.0f;
    if (s != d) {
        int deg = g_hs[s] + g_hd[s] + g_hs[d] + g_hd[d]
                - 2 * (g_sl[s] + g_sl[d]);             // integer-exact, >= 2
        int dir;
        if (g_flagA)       dir = ((const unsigned char*)isdir)[e] != 0;
        else if (g_flagNZ) dir = ((const int*)isdir)[e] != 0;
        else               dir = 0;
        float sgn = dir ? -1.0f : 1.0f;
        w = sgn * rsqrtf((float)deg);
    }
    g_w[e] = w;
}

// ============ K3: scatter t[src] -= w*x, t[dst] += w*x =====================
// thread per (edge, float4-chunk): E*64 threads
__global__ __launch_bounds__(256)
void k_scatter(const float* __restrict__ x, const int* __restrict__ ei, int E) {
    int t = blockIdx.x * blockDim.x + threadIdx.x;
    int e  = t >> 6;
    int c4 = t & 63;
    if (e >= E) return;
    float w = g_w[e];
    if (w == 0.0f) return;
    float4 v = ((const float4*)x)[e * FC4 + c4];
    int s = ei[e], d = ei[E + e];
    float* ts = &g_t[s * FC + c4 * 4];
    float* td = &g_t[d * FC + c4 * 4];
    atomicAdd(&ts[0], -w * v.x); atomicAdd(&ts[1], -w * v.y);
    atomicAdd(&ts[2], -w * v.z); atomicAdd(&ts[3], -w * v.w);
    atomicAdd(&td[0],  w * v.x); atomicAdd(&td[1],  w * v.y);
    atomicAdd(&td[2],  w * v.z); atomicAdd(&td[3],  w * v.w);
}

// ============ K4: GEMM  T[m][n] = sum_k t[m][k] * W[n][k] ==================
// M=NN=1024, N=FC=256, K=FC=256.  BM=32, BN=64, BK=16 -> 128 blocks x 128 thr
#define BM 32
#define BN 64
#define BK 16
__global__ __launch_bounds__(128)
void k_gemm(const float* __restrict__ B /* W [N,K] */) {
    __shared__ float As[BK][BM + 1];
    __shared__ float Bs[BK][BN + 1];
    int gx = blockIdx.x & 3;          // 4 col tiles
    int gy = blockIdx.x >> 2;         // 32 row tiles
    int m0 = gy * BM;
    int n0 = gx * BN;
    int tid = threadIdx.x;
    int tx = tid & 15;                // 16 col groups of 4
    int ty = tid >> 4;                // 8 row groups of 4

    float acc[4][4];
    #pragma unroll
    for (int i = 0; i < 4; i++)
        #pragma unroll
        for (int j = 0; j < 4; j++) acc[i][j] = 0.0f;

    for (int k0 = 0; k0 < FC; k0 += BK) {
        {   // A tile: 32x16 = 128 float4, one per thread
            int row = tid >> 2;
            int kq  = (tid & 3) << 2;
            float4 v = *(const float4*)&g_t[(m0 + row) * FC + k0 + kq];
            As[kq + 0][row] = v.x; As[kq + 1][row] = v.y;
            As[kq + 2][row] = v.z; As[kq + 3][row] = v.w;
        }
        #pragma unroll
        for (int r = 0; r < 2; r++) {  // B tile: 64x16 = 256 float4
            int idx = tid + 128 * r;
            int n   = idx >> 2;
            int kq  = (idx & 3) << 2;
            float4 v = *(const float4*)&B[(n0 + n) * FC + k0 + kq];
            Bs[kq + 0][n] = v.x; Bs[kq + 1][n] = v.y;
            Bs[kq + 2][n] = v.z; Bs[kq + 3][n] = v.w;
        }
        __syncthreads();

        #pragma unroll
        for (int k = 0; k < BK; k++) {
            float a[4], bb[4];
            #pragma unroll
            for (int i = 0; i < 4; i++) a[i]  = As[k][ty * 4 + i];
            #pragma unroll
            for (int j = 0; j < 4; j++) bb[j] = Bs[k][tx * 4 + j];
            #pragma unroll
            for (int i = 0; i < 4; i++)
                #pragma unroll
                for (int j = 0; j < 4; j++)
                    acc[i][j] = fmaf(a[i], bb[j], acc[i][j]);
        }
        __syncthreads();
    }

    #pragma unroll
    for (int i = 0; i < 4; i++) {
        float4 v = make_float4(acc[i][0], acc[i][1], acc[i][2], acc[i][3]);
        *(float4*)&g_T[(m0 + ty * 4 + i) * FC + n0 + tx * 4] = v;
    }
}

// ============ K5: gather  y_e = w_e * (T[dst_e] - T[src_e]) ================
__global__ __launch_bounds__(256)
void k_gather(const int* __restrict__ ei, float* __restrict__ y, int E) {
    int t = blockIdx.x * blockDim.x + threadIdx.x;
    int e  = t >> 6;
    int c4 = t & 63;
    if (e >= E) return;
    float w = g_w[e];
    int s = ei[e], d = ei[E + e];
    float4 vd = ((const float4*)g_T)[d * FC4 + c4];
    float4 vs = ((const float4*)g_T)[s * FC4 + c4];
    float4 o;
    o.x = w * (vd.x - vs.x); o.y = w * (vd.y - vs.y);
    o.z = w * (vd.z - vs.z); o.w = w * (vd.w - vs.w);
    ((float4*)y)[e * FC4 + c4] = o;
}

// ---------------- launch ---------------------------------------------------
extern "C" void kernel_launch(void* const* d_in, const int* in_sizes, int n_in,
                              void* d_out, int out_size) {
    const float* x     = (const float*)d_in[0];   // [E, 256]
    const float* W     = (const float*)d_in[1];   // [256, 256]
    const int*   ei    = (const int*)d_in[2];     // [2, E]
    const void*  isdir = d_in[3];                 // [E] bool or int32

    int E = in_sizes[2] / 2;
    float* y = (float*)d_out;

    k_zero<<<256, 256>>>();                                   // 65536 threads
    k_hist<<<(E + 255) / 256, 256>>>(ei, (const unsigned char*)isdir, E);
    k_wgt<<<(E + 255) / 256, 256>>>(ei, isdir, E);
    k_scatter<<<(E * FC4 + 255) / 256, 256>>>(x, ei, E);      // 1024 blocks
    k_gemm<<<128, 128>>>(W);                                  // T = t @ W^T
    k_gather<<<(E * FC4 + 255) / 256, 256>>>(ei, y, E);       // 1024 blocks
}